// round 6
// baseline (speedup 1.0000x reference)
#include <cuda_runtime.h>
#include <cuda_bf16.h>
#include <cuda_fp16.h>
#include <cstdint>
#include <math.h>

// ---------------------------------------------------------------------------
// Problem constants
// ---------------------------------------------------------------------------
#define B_    16
#define Hh    56
#define Ww    56
#define Nn    3136
#define C_    384
#define C3    1152
#define HEADS_ 12
#define HD    32
#define WS_   7
#define WT    49
#define WG    8
#define NW    64
#define M_ROWS (B_*Nn)      // 50176

// ---------------------------------------------------------------------------
// Scratch (__device__ globals; no allocations allowed)
// ---------------------------------------------------------------------------
__device__ float g_qkv[(size_t)M_ROWS * C3];   // fp32 q|k|v
__device__ float g_y  [(size_t)M_ROWS * C_];   // attn out + LIM (fp32)
__device__ __half g_wqh[C_ * C3];
__device__ __half g_wql[C_ * C3];
__device__ __half g_wph[C_ * C_];
__device__ __half g_wpl[C_ * C_];

// ---------------------------------------------------------------------------
// helpers
// ---------------------------------------------------------------------------
__device__ __forceinline__ uint32_t smem_u32(const void* p) {
    return (uint32_t)__cvta_generic_to_shared(p);
}
__device__ __forceinline__ void ldsm4(uint32_t* r, uint32_t addr) {
    asm volatile("ldmatrix.sync.aligned.m8n8.x4.shared.b16 {%0,%1,%2,%3}, [%4];\n"
                 : "=r"(r[0]), "=r"(r[1]), "=r"(r[2]), "=r"(r[3]) : "r"(addr));
}
__device__ __forceinline__ void ldsm4t(uint32_t* r, uint32_t addr) {
    asm volatile("ldmatrix.sync.aligned.m8n8.x4.trans.shared.b16 {%0,%1,%2,%3}, [%4];\n"
                 : "=r"(r[0]), "=r"(r[1]), "=r"(r[2]), "=r"(r[3]) : "r"(addr));
}
__device__ __forceinline__ void mma_fp16(float* c, const uint32_t* a,
                                         uint32_t b0, uint32_t b1) {
    asm volatile(
        "mma.sync.aligned.m16n8k16.row.col.f32.f16.f16.f32 "
        "{%0,%1,%2,%3}, {%4,%5,%6,%7}, {%8,%9}, {%0,%1,%2,%3};\n"
        : "+f"(c[0]), "+f"(c[1]), "+f"(c[2]), "+f"(c[3])
        : "r"(a[0]), "r"(a[1]), "r"(a[2]), "r"(a[3]), "r"(b0), "r"(b1));
}
__device__ __forceinline__ void cpasync16(uint32_t dst, const void* src) {
    asm volatile("cp.async.cg.shared.global [%0], [%1], 16;" :: "r"(dst), "l"(src));
}
__device__ __forceinline__ void cp_commit() {
    asm volatile("cp.async.commit_group;" ::: "memory");
}
__device__ __forceinline__ void cp_wait0() {
    asm volatile("cp.async.wait_group 0;" ::: "memory");
}

// ---------------------------------------------------------------------------
// Weight prep: fp32 [K][N] -> fp16 hi [K][N] + fp16 lo [K][N]
// ---------------------------------------------------------------------------
__global__ __launch_bounds__(256)
void prep_half_kernel(const float* __restrict__ w, __half* __restrict__ hi,
                      __half* __restrict__ lo, int n4)
{
    int i = blockIdx.x * blockDim.x + threadIdx.x;
    if (i >= n4) return;
    float4 v = reinterpret_cast<const float4*>(w)[i];
    union { __half h[4]; uint2 u; } hu, lu;
    float f[4] = {v.x, v.y, v.z, v.w};
#pragma unroll
    for (int j = 0; j < 4; j++) {
        __half hb = __float2half_rn(f[j]);
        hu.h[j] = hb;
        lu.h[j] = __float2half_rn(f[j] - __half2float(hb));
    }
    reinterpret_cast<uint2*>(hi)[i] = hu.u;
    reinterpret_cast<uint2*>(lo)[i] = lu.u;
}

// ---------------------------------------------------------------------------
// fp16 split HMMA GEMM.  C[M,N] = A_f32[M,K] @ B (+ bias)
//   TERMS==3: Ah*Bh + Al*Bh + Ah*Bl   (residual ~2^-22)
//   TERMS==2: Ah*Bh + Al*Bh           (= A * Bh, err ~2^-12 on B)
// Bh/Bl are pre-converted fp16 [K][N].  A split fused in-register.
// Block tile 128x128x32, 512 threads (16 warps, 32x32 warp tiles),
// double-buffered smem, cp.async for B.
// M%128==0, N%128==0, K%32==0, K/32>=2.
// ---------------------------------------------------------------------------
#define ABUF 10240             // 128x40 halves (bytes)
#define BBUF 8704              // 32x136 halves (bytes)
#define OFF_AHB 0
#define OFF_ALB (2*ABUF)
#define OFF_BHB (4*ABUF)
#define OFF_BLB (4*ABUF + 2*BBUF)
#define SMEM_T3 (4*ABUF + 4*BBUF)   // 75776
#define SMEM_T2 (4*ABUF + 2*BBUF)   // 58368

template<int TERMS>
__global__ __launch_bounds__(512)
void hgemm(const float* __restrict__ A, const __half* __restrict__ Bh16,
           const __half* __restrict__ Bl16, float* __restrict__ C,
           int M, int N, int K, const float* __restrict__ bias)
{
    extern __shared__ char smem[];
    const uint32_t sb = smem_u32(smem);
    const int tid  = threadIdx.x;
    const int lane = tid & 31;
    const int warp = tid >> 5;
    const int wm = (warp >> 2) * 32;   // warp row offset (0..96)
    const int wn = (warp & 3) * 32;    // warp col offset (0..96)
    const int bx = blockIdx.x, by = blockIdx.y;

    const float*  Ag  = A    + (size_t)by * 128 * K;
    const __half* Bgh = Bh16 + (size_t)bx * 128;
    const __half* Bgl = Bl16 + (size_t)bx * 128;

    const int ntiles = K / 32;
    float4 ra[2];

    auto issueB = [&](int buf, int k0) {
        int r = tid >> 4, c8 = (tid & 15) * 8;          // 32 rows x 16 segs
        uint32_t off = (uint32_t)(r * 136 + c8) * 2;
        cpasync16(sb + OFF_BHB + buf * BBUF + off, Bgh + (size_t)(k0 + r) * N + c8);
        if (TERMS == 3)
            cpasync16(sb + OFF_BLB + buf * BBUF + off, Bgl + (size_t)(k0 + r) * N + c8);
        cp_commit();
    };
    auto loadA = [&](int k0) {
#pragma unroll
        for (int i = 0; i < 2; i++) {
            int seg = tid + i * 512;                    // 0..1023
            int r = seg >> 3, c4 = (seg & 7) * 4;
            ra[i] = *reinterpret_cast<const float4*>(Ag + (size_t)r * K + k0 + c4);
        }
    };
    auto storeA = [&](int buf) {
#pragma unroll
        for (int i = 0; i < 2; i++) {
            int seg = tid + i * 512;
            int r = seg >> 3, c4 = (seg & 7) * 4;
            union { __half h[4]; uint64_t u; } hu, lu;
            float f[4] = {ra[i].x, ra[i].y, ra[i].z, ra[i].w};
#pragma unroll
            for (int j = 0; j < 4; j++) {
                __half hb = __float2half_rn(f[j]);
                hu.h[j] = hb;
                lu.h[j] = __float2half_rn(f[j] - __half2float(hb));
            }
            uint32_t off = (uint32_t)(r * 40 + c4) * 2;
            asm volatile("st.shared.b64 [%0], %1;"
                         :: "r"(sb + OFF_AHB + buf * ABUF + off), "l"(hu.u) : "memory");
            asm volatile("st.shared.b64 [%0], %1;"
                         :: "r"(sb + OFF_ALB + buf * ABUF + off), "l"(lu.u) : "memory");
        }
    };

    float acc[2][4][4];
#pragma unroll
    for (int mt = 0; mt < 2; mt++)
#pragma unroll
        for (int nt = 0; nt < 4; nt++)
#pragma unroll
            for (int j = 0; j < 4; j++) acc[mt][nt][j] = 0.f;

    issueB(0, 0);
    loadA(0);
    storeA(0);
    cp_wait0();
    __syncthreads();

    for (int kt = 0; kt < ntiles; kt++) {
        const int buf = kt & 1;
        const bool more = (kt + 1 < ntiles);
        if (more) { issueB(1 - buf, (kt + 1) * 32); loadA((kt + 1) * 32); }

        const uint32_t ah_b = sb + OFF_AHB + buf * ABUF;
        const uint32_t al_b = sb + OFF_ALB + buf * ABUF;
        const uint32_t bh_b = sb + OFF_BHB + buf * BBUF;
        const uint32_t bl_b = sb + OFF_BLB + buf * BBUF;
#pragma unroll
        for (int ks = 0; ks < 2; ks++) {
            const int kk = ks * 16;
            uint32_t ah[2][4], al[2][4], bh[2][4], bl[2][4];
#pragma unroll
            for (int mt = 0; mt < 2; mt++) {
                uint32_t off = (uint32_t)((wm + mt * 16 + (lane & 15)) * 40
                                          + kk + ((lane >> 4) << 3)) * 2;
                ldsm4(ah[mt], ah_b + off);
                ldsm4(al[mt], al_b + off);
            }
#pragma unroll
            for (int bt = 0; bt < 2; bt++) {
                uint32_t off = (uint32_t)((kk + (lane & 15)) * 136
                                          + wn + bt * 16 + ((lane >> 4) << 3)) * 2;
                ldsm4t(bh[bt], bh_b + off);
                if (TERMS == 3) ldsm4t(bl[bt], bl_b + off);
            }
#pragma unroll
            for (int mt = 0; mt < 2; mt++)
#pragma unroll
                for (int nt = 0; nt < 4; nt++) {
                    uint32_t b0 = bh[nt >> 1][(nt & 1) * 2];
                    uint32_t b1 = bh[nt >> 1][(nt & 1) * 2 + 1];
                    mma_fp16(acc[mt][nt], ah[mt], b0, b1);
                    mma_fp16(acc[mt][nt], al[mt], b0, b1);
                    if (TERMS == 3) {
                        uint32_t l0 = bl[nt >> 1][(nt & 1) * 2];
                        uint32_t l1 = bl[nt >> 1][(nt & 1) * 2 + 1];
                        mma_fp16(acc[mt][nt], ah[mt], l0, l1);
                    }
                }
        }

        if (more) {
            storeA(1 - buf);
            cp_wait0();
            __syncthreads();
        }
    }

#pragma unroll
    for (int mt = 0; mt < 2; mt++) {
        int r0 = by * 128 + wm + mt * 16 + (lane >> 2);
#pragma unroll
        for (int nt = 0; nt < 4; nt++) {
            int c0 = bx * 128 + wn + nt * 8 + (lane & 3) * 2;
            float bb0 = bias ? bias[c0] : 0.f;
            float bb1 = bias ? bias[c0 + 1] : 0.f;
            float2 v0 = {acc[mt][nt][0] + bb0, acc[mt][nt][1] + bb1};
            float2 v1 = {acc[mt][nt][2] + bb0, acc[mt][nt][3] + bb1};
            *reinterpret_cast<float2*>(&C[(size_t)r0 * N + c0]) = v0;
            *reinterpret_cast<float2*>(&C[(size_t)(r0 + 8) * N + c0]) = v1;
        }
    }
}

// ---------------------------------------------------------------------------
// Window attention + fused depthwise conv.
// One block per (batch, window, head), 64 threads; thread t<49 owns token t.
// Online softmax (scores bounded, no max subtraction, no s[] array).
// y = attn_out + conv(v) written once.
// ---------------------------------------------------------------------------
__global__ __launch_bounds__(64)
void attn_conv_kernel(const float* __restrict__ qkv,
                      const float* __restrict__ wconv,
                      const float* __restrict__ bconv,
                      float* __restrict__ y)
{
    int blk  = blockIdx.x;
    int head = blk % HEADS_;
    int w    = (blk / HEADS_) % NW;
    int b    = blk / (HEADS_ * NW);
    int wy = w / WG, wx = w % WG;

    __shared__ float ks[WT][HD];
    __shared__ float vs[WT][HD];

    int tid = threadIdx.x;
    for (int idx = tid; idx < WT * (HD / 4); idx += 64) {
        int j = idx >> 3, d4 = (idx & 7) * 4;
        int n = (wy * WS_ + j / WS_) * Ww + wx * WS_ + (j % WS_);
        size_t base = ((size_t)b * Nn + n) * C3 + head * HD + d4;
        *reinterpret_cast<float4*>(&ks[j][d4]) =
            *reinterpret_cast<const float4*>(qkv + base + C_);
        *reinterpret_cast<float4*>(&vs[j][d4]) =
            *reinterpret_cast<const float4*>(qkv + base + 2 * C_);
    }
    __syncthreads();

    if (tid >= WT) return;
    int n = (wy * WS_ + tid / WS_) * Ww + wx * WS_ + (tid % WS_);
    const float* qp = qkv + ((size_t)b * Nn + n) * C3 + head * HD;

    float q[HD];
#pragma unroll
    for (int d4 = 0; d4 < HD; d4 += 4) {
        float4 v = *reinterpret_cast<const float4*>(qp + d4);
        q[d4] = v.x; q[d4 + 1] = v.y; q[d4 + 2] = v.z; q[d4 + 3] = v.w;
    }

    const float scale = 0.1767766952966369f;  // 1/sqrt(32)
    float sum = 0.f;
    float o[HD];
#pragma unroll
    for (int d = 0; d < HD; d++) o[d] = 0.f;

#pragma unroll 7
    for (int j = 0; j < WT; j++) {
        float sc = 0.f;
#pragma unroll
        for (int d = 0; d < HD; d++) sc = fmaf(q[d], ks[j][d], sc);
        float p = __expf(sc * scale);    // |sc*scale| bounded (~12) -> safe
        sum += p;
#pragma unroll
        for (int d = 0; d < HD; d++) o[d] = fmaf(p, vs[j][d], o[d]);
    }
    float inv = 1.f / sum;

    // fused depthwise 3x3 conv on v for this token's 32 channels
    int h = n / Ww, w2 = n % Ww;
    int c0 = head * HD;
    float* yp = y + ((size_t)b * Nn + n) * C_ + c0;
#pragma unroll
    for (int d4 = 0; d4 < HD; d4 += 4) {
        float4 a = *reinterpret_cast<const float4*>(bconv + c0 + d4);
#pragma unroll
        for (int ky = 0; ky < 3; ky++) {
            int hy = h + ky - 1;
            if (hy < 0 || hy >= Hh) continue;
#pragma unroll
            for (int kx = 0; kx < 3; kx++) {
                int wx2 = w2 + kx - 1;
                if (wx2 < 0 || wx2 >= Ww) continue;
                float4 vv = *reinterpret_cast<const float4*>(
                    qkv + ((size_t)b * Nn + hy * Ww + wx2) * C3 + 2 * C_ + c0 + d4);
                float4 wc = *reinterpret_cast<const float4*>(
                    wconv + (ky * 3 + kx) * C_ + c0 + d4);
                a.x = fmaf(vv.x, wc.x, a.x);
                a.y = fmaf(vv.y, wc.y, a.y);
                a.z = fmaf(vv.z, wc.z, a.z);
                a.w = fmaf(vv.w, wc.w, a.w);
            }
        }
        float4 r = {o[d4] * inv + a.x, o[d4 + 1] * inv + a.y,
                    o[d4 + 2] * inv + a.z, o[d4 + 3] * inv + a.w};
        *reinterpret_cast<float4*>(yp + d4) = r;
    }
}

// ---------------------------------------------------------------------------
// Launch
// ---------------------------------------------------------------------------
extern "C" void kernel_launch(void* const* d_in, const int* in_sizes, int n_in,
                              void* d_out, int out_size)
{
    const float* x      = (const float*)d_in[0];
    const float* w_qkv  = (const float*)d_in[1];
    const float* w_proj = (const float*)d_in[2];
    const float* b_proj = (const float*)d_in[3];
    const float* w_conv = (const float*)d_in[4];
    const float* b_conv = (const float*)d_in[5];
    float* out = (float*)d_out;

    float *qkv, *y;
    __half *wqh, *wql, *wph, *wpl;
    cudaGetSymbolAddress((void**)&qkv, g_qkv);
    cudaGetSymbolAddress((void**)&y,   g_y);
    cudaGetSymbolAddress((void**)&wqh, g_wqh);
    cudaGetSymbolAddress((void**)&wql, g_wql);
    cudaGetSymbolAddress((void**)&wph, g_wph);
    cudaGetSymbolAddress((void**)&wpl, g_wpl);

    cudaFuncSetAttribute(hgemm<3>, cudaFuncAttributeMaxDynamicSharedMemorySize, SMEM_T3);
    cudaFuncSetAttribute(hgemm<2>, cudaFuncAttributeMaxDynamicSharedMemorySize, SMEM_T2);

    // 0) weight prep (fp32 -> fp16 hi/lo)
    prep_half_kernel<<<(C_ * C3 / 4 + 255) / 256, 256>>>(w_qkv, wqh, wql, C_ * C3 / 4);
    prep_half_kernel<<<(C_ * C_ / 4 + 255) / 256, 256>>>(w_proj, wph, wpl, C_ * C_ / 4);

    // 1) QKV GEMM, 3-term fp16 split: (50176,384) @ (384,1152)
    {
        dim3 grid(C3 / 128, M_ROWS / 128);
        hgemm<3><<<grid, 512, SMEM_T3>>>(x, wqh, wql, qkv, M_ROWS, C3, C_, nullptr);
    }
    // 2) window attention + fused depthwise conv -> y
    attn_conv_kernel<<<B_ * NW * HEADS_, 64>>>(qkv, w_conv, b_conv, y);
    // 3) proj GEMM, 2-term fp16 split (+bias) -> out
    {
        dim3 grid(C_ / 128, M_ROWS / 128);
        hgemm<2><<<grid, 512, SMEM_T2>>>(y, wph, wpl, out, M_ROWS, C_, C_, b_proj);
    }
}

// round 7
// speedup vs baseline: 1.3609x; 1.3609x over previous
#include <cuda_runtime.h>
#include <cuda_fp16.h>
#include <cstdint>
#include <math.h>

// ---------------------------------------------------------------------------
// Problem constants
// ---------------------------------------------------------------------------
#define B_    16
#define Hh    56
#define Ww    56
#define Nn    3136
#define C_    384
#define C3    1152
#define HEADS_ 12
#define HD    32
#define WS_   7
#define WT    49
#define WG    8
#define NW    64
#define M_ROWS (B_*Nn)      // 50176

// ---------------------------------------------------------------------------
// Scratch (__device__ globals; no allocations allowed)
// ---------------------------------------------------------------------------
__device__ float g_qkv[(size_t)M_ROWS * C3];   // fp32 q|k|v
__device__ float g_y  [(size_t)M_ROWS * C_];   // attn out + LIM (fp32)
__device__ __half g_wqh[C_ * C3];              // fp16 weights (hi only, 2-term)
__device__ __half g_wph[C_ * C_];

// ---------------------------------------------------------------------------
// helpers
// ---------------------------------------------------------------------------
__device__ __forceinline__ uint32_t smem_u32(const void* p) {
    return (uint32_t)__cvta_generic_to_shared(p);
}
__device__ __forceinline__ void ldsm4(uint32_t* r, uint32_t addr) {
    asm volatile("ldmatrix.sync.aligned.m8n8.x4.shared.b16 {%0,%1,%2,%3}, [%4];\n"
                 : "=r"(r[0]), "=r"(r[1]), "=r"(r[2]), "=r"(r[3]) : "r"(addr));
}
__device__ __forceinline__ void ldsm4t(uint32_t* r, uint32_t addr) {
    asm volatile("ldmatrix.sync.aligned.m8n8.x4.trans.shared.b16 {%0,%1,%2,%3}, [%4];\n"
                 : "=r"(r[0]), "=r"(r[1]), "=r"(r[2]), "=r"(r[3]) : "r"(addr));
}
__device__ __forceinline__ void mma_fp16(float* c, const uint32_t* a,
                                         uint32_t b0, uint32_t b1) {
    asm volatile(
        "mma.sync.aligned.m16n8k16.row.col.f32.f16.f16.f32 "
        "{%0,%1,%2,%3}, {%4,%5,%6,%7}, {%8,%9}, {%0,%1,%2,%3};\n"
        : "+f"(c[0]), "+f"(c[1]), "+f"(c[2]), "+f"(c[3])
        : "r"(a[0]), "r"(a[1]), "r"(a[2]), "r"(a[3]), "r"(b0), "r"(b1));
}
__device__ __forceinline__ void cpasync16(uint32_t dst, const void* src) {
    asm volatile("cp.async.cg.shared.global [%0], [%1], 16;" :: "r"(dst), "l"(src));
}
__device__ __forceinline__ void cp_commit() {
    asm volatile("cp.async.commit_group;" ::: "memory");
}
__device__ __forceinline__ void cp_wait0() {
    asm volatile("cp.async.wait_group 0;" ::: "memory");
}

// ---------------------------------------------------------------------------
// Weight prep: fp32 -> fp16 (round-to-nearest)
// ---------------------------------------------------------------------------
__global__ __launch_bounds__(256)
void prep_half_kernel(const float* __restrict__ w, __half* __restrict__ hi, int n4)
{
    int i = blockIdx.x * blockDim.x + threadIdx.x;
    if (i >= n4) return;
    float4 v = reinterpret_cast<const float4*>(w)[i];
    union { __half h[4]; uint2 u; } hu;
    hu.h[0] = __float2half_rn(v.x);
    hu.h[1] = __float2half_rn(v.y);
    hu.h[2] = __float2half_rn(v.z);
    hu.h[3] = __float2half_rn(v.w);
    reinterpret_cast<uint2*>(hi)[i] = hu.u;
}

// ---------------------------------------------------------------------------
// fp16 2-term split HMMA GEMM: C[M,N] = (Ah+Al)[M,K] @ Bh[K,N] (+ bias)
// A split fused in-register (A exact to ~2^-22); B pre-rounded to fp16.
// Block tile 128x128x32, 512 threads (16 warps, 32x32 warp tiles),
// double-buffered smem, cp.async for B.
// M%128==0, N%128==0, K%32==0, K/32>=2.
// ---------------------------------------------------------------------------
#define ABUF 10240             // 128x40 halves (bytes)
#define BBUF 8704              // 32x136 halves (bytes)
#define OFF_AHB 0
#define OFF_ALB (2*ABUF)
#define OFF_BHB (4*ABUF)
#define SMEM_G (4*ABUF + 2*BBUF)   // 58368

__global__ __launch_bounds__(512)
void hgemm(const float* __restrict__ A, const __half* __restrict__ Bh16,
           float* __restrict__ C, int M, int N, int K,
           const float* __restrict__ bias)
{
    extern __shared__ char smem[];
    const uint32_t sb = smem_u32(smem);
    const int tid  = threadIdx.x;
    const int lane = tid & 31;
    const int warp = tid >> 5;
    const int wm = (warp >> 2) * 32;   // warp row offset (0..96)
    const int wn = (warp & 3) * 32;    // warp col offset (0..96)
    const int bx = blockIdx.x, by = blockIdx.y;

    const float*  Ag  = A    + (size_t)by * 128 * K;
    const __half* Bgh = Bh16 + (size_t)bx * 128;

    const int ntiles = K / 32;
    float4 ra[2];

    auto issueB = [&](int buf, int k0) {
        int r = tid >> 4, c8 = (tid & 15) * 8;          // 32 rows x 16 segs
        uint32_t off = (uint32_t)(r * 136 + c8) * 2;
        cpasync16(sb + OFF_BHB + buf * BBUF + off, Bgh + (size_t)(k0 + r) * N + c8);
        cp_commit();
    };
    auto loadA = [&](int k0) {
#pragma unroll
        for (int i = 0; i < 2; i++) {
            int seg = tid + i * 512;                    // 0..1023
            int r = seg >> 3, c4 = (seg & 7) * 4;
            ra[i] = *reinterpret_cast<const float4*>(Ag + (size_t)r * K + k0 + c4);
        }
    };
    auto storeA = [&](int buf) {
#pragma unroll
        for (int i = 0; i < 2; i++) {
            int seg = tid + i * 512;
            int r = seg >> 3, c4 = (seg & 7) * 4;
            union { __half h[4]; uint64_t u; } hu, lu;
            float f[4] = {ra[i].x, ra[i].y, ra[i].z, ra[i].w};
#pragma unroll
            for (int j = 0; j < 4; j++) {
                __half hb = __float2half_rn(f[j]);
                hu.h[j] = hb;
                lu.h[j] = __float2half_rn(f[j] - __half2float(hb));
            }
            uint32_t off = (uint32_t)(r * 40 + c4) * 2;
            asm volatile("st.shared.b64 [%0], %1;"
                         :: "r"(sb + OFF_AHB + buf * ABUF + off), "l"(hu.u) : "memory");
            asm volatile("st.shared.b64 [%0], %1;"
                         :: "r"(sb + OFF_ALB + buf * ABUF + off), "l"(lu.u) : "memory");
        }
    };

    float acc[2][4][4];
#pragma unroll
    for (int mt = 0; mt < 2; mt++)
#pragma unroll
        for (int nt = 0; nt < 4; nt++)
#pragma unroll
            for (int j = 0; j < 4; j++) acc[mt][nt][j] = 0.f;

    issueB(0, 0);
    loadA(0);
    storeA(0);
    cp_wait0();
    __syncthreads();

    for (int kt = 0; kt < ntiles; kt++) {
        const int buf = kt & 1;
        const bool more = (kt + 1 < ntiles);
        if (more) { issueB(1 - buf, (kt + 1) * 32); loadA((kt + 1) * 32); }

        const uint32_t ah_b = sb + OFF_AHB + buf * ABUF;
        const uint32_t al_b = sb + OFF_ALB + buf * ABUF;
        const uint32_t bh_b = sb + OFF_BHB + buf * BBUF;
#pragma unroll
        for (int ks = 0; ks < 2; ks++) {
            const int kk = ks * 16;
            uint32_t ah[2][4], al[2][4], bh[2][4];
#pragma unroll
            for (int mt = 0; mt < 2; mt++) {
                uint32_t off = (uint32_t)((wm + mt * 16 + (lane & 15)) * 40
                                          + kk + ((lane >> 4) << 3)) * 2;
                ldsm4(ah[mt], ah_b + off);
                ldsm4(al[mt], al_b + off);
            }
#pragma unroll
            for (int bt = 0; bt < 2; bt++) {
                uint32_t off = (uint32_t)((kk + (lane & 15)) * 136
                                          + wn + bt * 16 + ((lane >> 4) << 3)) * 2;
                ldsm4t(bh[bt], bh_b + off);
            }
#pragma unroll
            for (int mt = 0; mt < 2; mt++)
#pragma unroll
                for (int nt = 0; nt < 4; nt++) {
                    uint32_t b0 = bh[nt >> 1][(nt & 1) * 2];
                    uint32_t b1 = bh[nt >> 1][(nt & 1) * 2 + 1];
                    mma_fp16(acc[mt][nt], ah[mt], b0, b1);
                    mma_fp16(acc[mt][nt], al[mt], b0, b1);
                }
        }

        if (more) {
            storeA(1 - buf);
            cp_wait0();
            __syncthreads();
        }
    }

#pragma unroll
    for (int mt = 0; mt < 2; mt++) {
        int r0 = by * 128 + wm + mt * 16 + (lane >> 2);
#pragma unroll
        for (int nt = 0; nt < 4; nt++) {
            int c0 = bx * 128 + wn + nt * 8 + (lane & 3) * 2;
            float bb0 = bias ? bias[c0] : 0.f;
            float bb1 = bias ? bias[c0 + 1] : 0.f;
            float2 v0 = {acc[mt][nt][0] + bb0, acc[mt][nt][1] + bb1};
            float2 v1 = {acc[mt][nt][2] + bb0, acc[mt][nt][3] + bb1};
            *reinterpret_cast<float2*>(&C[(size_t)r0 * N + c0]) = v0;
            *reinterpret_cast<float2*>(&C[(size_t)(r0 + 8) * N + c0]) = v1;
        }
    }
}

// ---------------------------------------------------------------------------
// Window attention: one block per (batch, window, head), 64 threads.
// Online softmax without max-subtraction (scores ~N(0, 0.15), safe).
// ---------------------------------------------------------------------------
__global__ __launch_bounds__(64)
void attn_kernel(const float* __restrict__ qkv, float* __restrict__ y)
{
    int blk  = blockIdx.x;
    int head = blk % HEADS_;
    int w    = (blk / HEADS_) % NW;
    int b    = blk / (HEADS_ * NW);
    int wy = w / WG, wx = w % WG;

    __shared__ float ks[WT][HD];
    __shared__ float vs[WT][HD];

    int tid = threadIdx.x;
    for (int idx = tid; idx < WT * (HD / 4); idx += 64) {
        int j = idx >> 3, d4 = (idx & 7) * 4;
        int n = (wy * WS_ + j / WS_) * Ww + wx * WS_ + (j % WS_);
        size_t base = ((size_t)b * Nn + n) * C3 + head * HD + d4;
        *reinterpret_cast<float4*>(&ks[j][d4]) =
            *reinterpret_cast<const float4*>(qkv + base + C_);
        *reinterpret_cast<float4*>(&vs[j][d4]) =
            *reinterpret_cast<const float4*>(qkv + base + 2 * C_);
    }
    __syncthreads();

    if (tid >= WT) return;
    int n = (wy * WS_ + tid / WS_) * Ww + wx * WS_ + (tid % WS_);
    const float* qp = qkv + ((size_t)b * Nn + n) * C3 + head * HD;

    float q[HD];
#pragma unroll
    for (int d4 = 0; d4 < HD; d4 += 4) {
        float4 v = *reinterpret_cast<const float4*>(qp + d4);
        q[d4] = v.x; q[d4 + 1] = v.y; q[d4 + 2] = v.z; q[d4 + 3] = v.w;
    }

    const float scale = 0.1767766952966369f;  // 1/sqrt(32)
    float sum = 0.f;
    float o[HD];
#pragma unroll
    for (int d = 0; d < HD; d++) o[d] = 0.f;

#pragma unroll 7
    for (int j = 0; j < WT; j++) {
        float sc = 0.f;
#pragma unroll
        for (int d = 0; d < HD; d++) sc = fmaf(q[d], ks[j][d], sc);
        float p = __expf(sc * scale);
        sum += p;
#pragma unroll
        for (int d = 0; d < HD; d++) o[d] = fmaf(p, vs[j][d], o[d]);
    }
    float inv = 1.f / sum;

    float* yp = y + ((size_t)b * Nn + n) * C_ + head * HD;
#pragma unroll
    for (int d4 = 0; d4 < HD; d4 += 4) {
        float4 v = {o[d4] * inv, o[d4 + 1] * inv, o[d4 + 2] * inv, o[d4 + 3] * inv};
        *reinterpret_cast<float4*>(yp + d4) = v;
    }
}

// ---------------------------------------------------------------------------
// Depthwise 3x3 conv (SAME) over v, accumulated into y. float4 over channels.
// ---------------------------------------------------------------------------
__global__ __launch_bounds__(256)
void conv_add_kernel(const float* __restrict__ qkv, const float* __restrict__ wconv,
                     const float* __restrict__ bconv, float* __restrict__ y)
{
    const int C4 = C_ / 4;
    long long idx = (long long)blockIdx.x * blockDim.x + threadIdx.x;
    if (idx >= (long long)B_ * Nn * C4) return;
    int c4 = (int)(idx % C4);
    int n  = (int)((idx / C4) % Nn);
    int b  = (int)(idx / ((long long)C4 * Nn));
    int h = n / Ww, w = n % Ww;
    int c = c4 * 4;

    float4 acc = *reinterpret_cast<const float4*>(bconv + c);
#pragma unroll
    for (int ky = 0; ky < 3; ky++) {
        int hy = h + ky - 1;
        if (hy < 0 || hy >= Hh) continue;
#pragma unroll
        for (int kx = 0; kx < 3; kx++) {
            int wx2 = w + kx - 1;
            if (wx2 < 0 || wx2 >= Ww) continue;
            float4 vv = *reinterpret_cast<const float4*>(
                qkv + ((size_t)b * Nn + hy * Ww + wx2) * C3 + 2 * C_ + c);
            float4 wc = *reinterpret_cast<const float4*>(
                wconv + (ky * 3 + kx) * C_ + c);
            acc.x = fmaf(vv.x, wc.x, acc.x);
            acc.y = fmaf(vv.y, wc.y, acc.y);
            acc.z = fmaf(vv.z, wc.z, acc.z);
            acc.w = fmaf(vv.w, wc.w, acc.w);
        }
    }
    float4* yp = reinterpret_cast<float4*>(y + ((size_t)b * Nn + n) * C_ + c);
    float4 old = *yp;
    old.x += acc.x; old.y += acc.y; old.z += acc.z; old.w += acc.w;
    *yp = old;
}

// ---------------------------------------------------------------------------
// Launch
// ---------------------------------------------------------------------------
extern "C" void kernel_launch(void* const* d_in, const int* in_sizes, int n_in,
                              void* d_out, int out_size)
{
    const float* x      = (const float*)d_in[0];
    const float* w_qkv  = (const float*)d_in[1];
    const float* w_proj = (const float*)d_in[2];
    const float* b_proj = (const float*)d_in[3];
    const float* w_conv = (const float*)d_in[4];
    const float* b_conv = (const float*)d_in[5];
    float* out = (float*)d_out;

    float *qkv, *y;
    __half *wqh, *wph;
    cudaGetSymbolAddress((void**)&qkv, g_qkv);
    cudaGetSymbolAddress((void**)&y,   g_y);
    cudaGetSymbolAddress((void**)&wqh, g_wqh);
    cudaGetSymbolAddress((void**)&wph, g_wph);

    cudaFuncSetAttribute(hgemm, cudaFuncAttributeMaxDynamicSharedMemorySize, SMEM_G);

    // 0) weight prep (fp32 -> fp16)
    prep_half_kernel<<<(C_ * C3 / 4 + 255) / 256, 256>>>(w_qkv, wqh, C_ * C3 / 4);
    prep_half_kernel<<<(C_ * C_ / 4 + 255) / 256, 256>>>(w_proj, wph, C_ * C_ / 4);

    // 1) QKV GEMM, 2-term fp16 split: (50176,384) @ (384,1152)
    {
        dim3 grid(C3 / 128, M_ROWS / 128);
        hgemm<<<grid, 512, SMEM_G>>>(x, wqh, qkv, M_ROWS, C3, C_, nullptr);
    }
    // 2) window attention -> y
    attn_kernel<<<B_ * NW * HEADS_, 64>>>(qkv, y);
    // 3) depthwise conv, += into y
    {
        long long total = (long long)B_ * Nn * (C_ / 4);
        conv_add_kernel<<<(unsigned)((total + 255) / 256), 256>>>(qkv, w_conv, b_conv, y);
    }
    // 4) proj GEMM, 2-term fp16 split (+bias) -> out
    {
        dim3 grid(C_ / 128, M_ROWS / 128);
        hgemm<<<grid, 512, SMEM_G>>>(y, wph, out, M_ROWS, C_, C_, b_proj);
    }
}

// round 8
// speedup vs baseline: 1.3623x; 1.0010x over previous
#include <cuda_runtime.h>
#include <cuda_fp16.h>
#include <cstdint>
#include <math.h>

// ---------------------------------------------------------------------------
// Problem constants
// ---------------------------------------------------------------------------
#define B_    16
#define Hh    56
#define Ww    56
#define Nn    3136
#define C_    384
#define C3    1152
#define HEADS_ 12
#define HD    32
#define WS_   7
#define WT    49
#define WG    8
#define NW    64
#define M_ROWS (B_*Nn)      // 50176

// ---------------------------------------------------------------------------
// Scratch (__device__ globals; no allocations allowed)
// ---------------------------------------------------------------------------
__device__ float g_qkv[(size_t)M_ROWS * C3];   // fp32 q|k|v
__device__ float g_y  [(size_t)M_ROWS * C_];   // attn out + LIM (fp32)
__device__ __half g_wqh[C_ * C3];              // fp16 weights (hi only, 2-term)
__device__ __half g_wph[C_ * C_];

// ---------------------------------------------------------------------------
// helpers
// ---------------------------------------------------------------------------
__device__ __forceinline__ uint32_t smem_u32(const void* p) {
    return (uint32_t)__cvta_generic_to_shared(p);
}
__device__ __forceinline__ void ldsm4(uint32_t* r, uint32_t addr) {
    asm volatile("ldmatrix.sync.aligned.m8n8.x4.shared.b16 {%0,%1,%2,%3}, [%4];\n"
                 : "=r"(r[0]), "=r"(r[1]), "=r"(r[2]), "=r"(r[3]) : "r"(addr));
}
__device__ __forceinline__ void ldsm4t(uint32_t* r, uint32_t addr) {
    asm volatile("ldmatrix.sync.aligned.m8n8.x4.trans.shared.b16 {%0,%1,%2,%3}, [%4];\n"
                 : "=r"(r[0]), "=r"(r[1]), "=r"(r[2]), "=r"(r[3]) : "r"(addr));
}
__device__ __forceinline__ void mma_fp16(float* c, const uint32_t* a,
                                         uint32_t b0, uint32_t b1) {
    asm volatile(
        "mma.sync.aligned.m16n8k16.row.col.f32.f16.f16.f32 "
        "{%0,%1,%2,%3}, {%4,%5,%6,%7}, {%8,%9}, {%0,%1,%2,%3};\n"
        : "+f"(c[0]), "+f"(c[1]), "+f"(c[2]), "+f"(c[3])
        : "r"(a[0]), "r"(a[1]), "r"(a[2]), "r"(a[3]), "r"(b0), "r"(b1));
}
__device__ __forceinline__ void cpasync16(uint32_t dst, const void* src) {
    asm volatile("cp.async.cg.shared.global [%0], [%1], 16;" :: "r"(dst), "l"(src));
}
__device__ __forceinline__ void cp_commit() {
    asm volatile("cp.async.commit_group;" ::: "memory");
}
__device__ __forceinline__ void cp_wait0() {
    asm volatile("cp.async.wait_group 0;" ::: "memory");
}

// FMA-pipe exp: e^x = 2^n * 2^f, n=rint(x*log2e), f in [-0.5,0.5].
// Degree-5 Taylor of 2^f in (ln2*f); rel err ~2.4e-6. No MUFU.
__device__ __forceinline__ float fast_exp(float x) {
    float t = x * 1.4426950408889634f;
    int   ni = __float2int_rn(t);
    float f  = t - (float)ni;
    float p =        1.3333558146428443e-3f;   // ln2^5/120
    p = fmaf(p, f,   9.6181291076284772e-3f);  // ln2^4/24
    p = fmaf(p, f,   5.5504108664821580e-2f);  // ln2^3/6
    p = fmaf(p, f,   2.4022650695910071e-1f);  // ln2^2/2
    p = fmaf(p, f,   6.9314718055994531e-1f);  // ln2
    p = fmaf(p, f,   1.0f);
    return p * __int_as_float((ni + 127) << 23);
}

// ---------------------------------------------------------------------------
// Weight prep: fp32 -> fp16 (round-to-nearest)
// ---------------------------------------------------------------------------
__global__ __launch_bounds__(256)
void prep_half_kernel(const float* __restrict__ w, __half* __restrict__ hi, int n4)
{
    int i = blockIdx.x * blockDim.x + threadIdx.x;
    if (i >= n4) return;
    float4 v = reinterpret_cast<const float4*>(w)[i];
    union { __half h[4]; uint2 u; } hu;
    hu.h[0] = __float2half_rn(v.x);
    hu.h[1] = __float2half_rn(v.y);
    hu.h[2] = __float2half_rn(v.z);
    hu.h[3] = __float2half_rn(v.w);
    reinterpret_cast<uint2*>(hi)[i] = hu.u;
}

// ---------------------------------------------------------------------------
// fp16 2-term split HMMA GEMM: C[M,N] = (Ah+Al)[M,K] @ Bh[K,N] (+ bias)
// Block tile 128x128x32, 512 threads, double-buffered smem, cp.async for B.
// ---------------------------------------------------------------------------
#define ABUF 10240             // 128x40 halves (bytes)
#define BBUF 8704              // 32x136 halves (bytes)
#define OFF_AHB 0
#define OFF_ALB (2*ABUF)
#define OFF_BHB (4*ABUF)
#define SMEM_G (4*ABUF + 2*BBUF)   // 58368

__global__ __launch_bounds__(512)
void hgemm(const float* __restrict__ A, const __half* __restrict__ Bh16,
           float* __restrict__ C, int M, int N, int K,
           const float* __restrict__ bias)
{
    extern __shared__ char smem[];
    const uint32_t sb = smem_u32(smem);
    const int tid  = threadIdx.x;
    const int lane = tid & 31;
    const int warp = tid >> 5;
    const int wm = (warp >> 2) * 32;
    const int wn = (warp & 3) * 32;
    const int bx = blockIdx.x, by = blockIdx.y;

    const float*  Ag  = A    + (size_t)by * 128 * K;
    const __half* Bgh = Bh16 + (size_t)bx * 128;

    const int ntiles = K / 32;
    float4 ra[2];

    auto issueB = [&](int buf, int k0) {
        int r = tid >> 4, c8 = (tid & 15) * 8;
        uint32_t off = (uint32_t)(r * 136 + c8) * 2;
        cpasync16(sb + OFF_BHB + buf * BBUF + off, Bgh + (size_t)(k0 + r) * N + c8);
        cp_commit();
    };
    auto loadA = [&](int k0) {
#pragma unroll
        for (int i = 0; i < 2; i++) {
            int seg = tid + i * 512;
            int r = seg >> 3, c4 = (seg & 7) * 4;
            ra[i] = *reinterpret_cast<const float4*>(Ag + (size_t)r * K + k0 + c4);
        }
    };
    auto storeA = [&](int buf) {
#pragma unroll
        for (int i = 0; i < 2; i++) {
            int seg = tid + i * 512;
            int r = seg >> 3, c4 = (seg & 7) * 4;
            union { __half h[4]; uint64_t u; } hu, lu;
            float f[4] = {ra[i].x, ra[i].y, ra[i].z, ra[i].w};
#pragma unroll
            for (int j = 0; j < 4; j++) {
                __half hb = __float2half_rn(f[j]);
                hu.h[j] = hb;
                lu.h[j] = __float2half_rn(f[j] - __half2float(hb));
            }
            uint32_t off = (uint32_t)(r * 40 + c4) * 2;
            asm volatile("st.shared.b64 [%0], %1;"
                         :: "r"(sb + OFF_AHB + buf * ABUF + off), "l"(hu.u) : "memory");
            asm volatile("st.shared.b64 [%0], %1;"
                         :: "r"(sb + OFF_ALB + buf * ABUF + off), "l"(lu.u) : "memory");
        }
    };

    float acc[2][4][4];
#pragma unroll
    for (int mt = 0; mt < 2; mt++)
#pragma unroll
        for (int nt = 0; nt < 4; nt++)
#pragma unroll
            for (int j = 0; j < 4; j++) acc[mt][nt][j] = 0.f;

    issueB(0, 0);
    loadA(0);
    storeA(0);
    cp_wait0();
    __syncthreads();

    for (int kt = 0; kt < ntiles; kt++) {
        const int buf = kt & 1;
        const bool more = (kt + 1 < ntiles);
        if (more) { issueB(1 - buf, (kt + 1) * 32); loadA((kt + 1) * 32); }

        const uint32_t ah_b = sb + OFF_AHB + buf * ABUF;
        const uint32_t al_b = sb + OFF_ALB + buf * ABUF;
        const uint32_t bh_b = sb + OFF_BHB + buf * BBUF;
#pragma unroll
        for (int ks = 0; ks < 2; ks++) {
            const int kk = ks * 16;
            uint32_t ah[2][4], al[2][4], bh[2][4];
#pragma unroll
            for (int mt = 0; mt < 2; mt++) {
                uint32_t off = (uint32_t)((wm + mt * 16 + (lane & 15)) * 40
                                          + kk + ((lane >> 4) << 3)) * 2;
                ldsm4(ah[mt], ah_b + off);
                ldsm4(al[mt], al_b + off);
            }
#pragma unroll
            for (int bt = 0; bt < 2; bt++) {
                uint32_t off = (uint32_t)((kk + (lane & 15)) * 136
                                          + wn + bt * 16 + ((lane >> 4) << 3)) * 2;
                ldsm4t(bh[bt], bh_b + off);
            }
#pragma unroll
            for (int mt = 0; mt < 2; mt++)
#pragma unroll
                for (int nt = 0; nt < 4; nt++) {
                    uint32_t b0 = bh[nt >> 1][(nt & 1) * 2];
                    uint32_t b1 = bh[nt >> 1][(nt & 1) * 2 + 1];
                    mma_fp16(acc[mt][nt], ah[mt], b0, b1);
                    mma_fp16(acc[mt][nt], al[mt], b0, b1);
                }
        }

        if (more) {
            storeA(1 - buf);
            cp_wait0();
            __syncthreads();
        }
    }

#pragma unroll
    for (int mt = 0; mt < 2; mt++) {
        int r0 = by * 128 + wm + mt * 16 + (lane >> 2);
#pragma unroll
        for (int nt = 0; nt < 4; nt++) {
            int c0 = bx * 128 + wn + nt * 8 + (lane & 3) * 2;
            float bb0 = bias ? bias[c0] : 0.f;
            float bb1 = bias ? bias[c0 + 1] : 0.f;
            float2 v0 = {acc[mt][nt][0] + bb0, acc[mt][nt][1] + bb1};
            float2 v1 = {acc[mt][nt][2] + bb0, acc[mt][nt][3] + bb1};
            *reinterpret_cast<float2*>(&C[(size_t)r0 * N + c0]) = v0;
            *reinterpret_cast<float2*>(&C[(size_t)(r0 + 8) * N + c0]) = v1;
        }
    }
}

// ---------------------------------------------------------------------------
// Window attention: one block per (batch, window, head), 64 threads.
// No-max online softmax; exp on the FMA pipe (fast_exp), zero MUFU.
// ---------------------------------------------------------------------------
__global__ __launch_bounds__(64)
void attn_kernel(const float* __restrict__ qkv, float* __restrict__ y)
{
    int blk  = blockIdx.x;
    int head = blk % HEADS_;
    int w    = (blk / HEADS_) % NW;
    int b    = blk / (HEADS_ * NW);
    int wy = w / WG, wx = w % WG;

    __shared__ float ks[WT][HD];
    __shared__ float vs[WT][HD];

    int tid = threadIdx.x;
    for (int idx = tid; idx < WT * (HD / 4); idx += 64) {
        int j = idx >> 3, d4 = (idx & 7) * 4;
        int n = (wy * WS_ + j / WS_) * Ww + wx * WS_ + (j % WS_);
        size_t base = ((size_t)b * Nn + n) * C3 + head * HD + d4;
        *reinterpret_cast<float4*>(&ks[j][d4]) =
            *reinterpret_cast<const float4*>(qkv + base + C_);
        *reinterpret_cast<float4*>(&vs[j][d4]) =
            *reinterpret_cast<const float4*>(qkv + base + 2 * C_);
    }
    __syncthreads();

    if (tid >= WT) return;
    int n = (wy * WS_ + tid / WS_) * Ww + wx * WS_ + (tid % WS_);
    const float* qp = qkv + ((size_t)b * Nn + n) * C3 + head * HD;

    float q[HD];
#pragma unroll
    for (int d4 = 0; d4 < HD; d4 += 4) {
        float4 v = *reinterpret_cast<const float4*>(qp + d4);
        q[d4] = v.x; q[d4 + 1] = v.y; q[d4 + 2] = v.z; q[d4 + 3] = v.w;
    }

    const float scale = 0.1767766952966369f;  // 1/sqrt(32)
    float sum = 0.f;
    float o[HD];
#pragma unroll
    for (int d = 0; d < HD; d++) o[d] = 0.f;

#pragma unroll 7
    for (int j = 0; j < WT; j++) {
        float sc = 0.f;
#pragma unroll
        for (int d = 0; d < HD; d++) sc = fmaf(q[d], ks[j][d], sc);
        float p = fast_exp(sc * scale);
        sum += p;
#pragma unroll
        for (int d = 0; d < HD; d++) o[d] = fmaf(p, vs[j][d], o[d]);
    }
    float inv = 1.f / sum;

    float* yp = y + ((size_t)b * Nn + n) * C_ + head * HD;
#pragma unroll
    for (int d4 = 0; d4 < HD; d4 += 4) {
        float4 v = {o[d4] * inv, o[d4 + 1] * inv, o[d4 + 2] * inv, o[d4 + 3] * inv};
        *reinterpret_cast<float4*>(yp + d4) = v;
    }
}

// ---------------------------------------------------------------------------
// Depthwise 3x3 conv (SAME) over v, accumulated into y. float4 over channels.
// ---------------------------------------------------------------------------
__global__ __launch_bounds__(256)
void conv_add_kernel(const float* __restrict__ qkv, const float* __restrict__ wconv,
                     const float* __restrict__ bconv, float* __restrict__ y)
{
    const int C4 = C_ / 4;
    long long idx = (long long)blockIdx.x * blockDim.x + threadIdx.x;
    if (idx >= (long long)B_ * Nn * C4) return;
    int c4 = (int)(idx % C4);
    int n  = (int)((idx / C4) % Nn);
    int b  = (int)(idx / ((long long)C4 * Nn));
    int h = n / Ww, w = n % Ww;
    int c = c4 * 4;

    float4 acc = *reinterpret_cast<const float4*>(bconv + c);
#pragma unroll
    for (int ky = 0; ky < 3; ky++) {
        int hy = h + ky - 1;
        if (hy < 0 || hy >= Hh) continue;
#pragma unroll
        for (int kx = 0; kx < 3; kx++) {
            int wx2 = w + kx - 1;
            if (wx2 < 0 || wx2 >= Ww) continue;
            float4 vv = *reinterpret_cast<const float4*>(
                qkv + ((size_t)b * Nn + hy * Ww + wx2) * C3 + 2 * C_ + c);
            float4 wc = *reinterpret_cast<const float4*>(
                wconv + (ky * 3 + kx) * C_ + c);
            acc.x = fmaf(vv.x, wc.x, acc.x);
            acc.y = fmaf(vv.y, wc.y, acc.y);
            acc.z = fmaf(vv.z, wc.z, acc.z);
            acc.w = fmaf(vv.w, wc.w, acc.w);
        }
    }
    float4* yp = reinterpret_cast<float4*>(y + ((size_t)b * Nn + n) * C_ + c);
    float4 old = *yp;
    old.x += acc.x; old.y += acc.y; old.z += acc.z; old.w += acc.w;
    *yp = old;
}

// ---------------------------------------------------------------------------
// Launch
// ---------------------------------------------------------------------------
extern "C" void kernel_launch(void* const* d_in, const int* in_sizes, int n_in,
                              void* d_out, int out_size)
{
    const float* x      = (const float*)d_in[0];
    const float* w_qkv  = (const float*)d_in[1];
    const float* w_proj = (const float*)d_in[2];
    const float* b_proj = (const float*)d_in[3];
    const float* w_conv = (const float*)d_in[4];
    const float* b_conv = (const float*)d_in[5];
    float* out = (float*)d_out;

    float *qkv, *y;
    __half *wqh, *wph;
    cudaGetSymbolAddress((void**)&qkv, g_qkv);
    cudaGetSymbolAddress((void**)&y,   g_y);
    cudaGetSymbolAddress((void**)&wqh, g_wqh);
    cudaGetSymbolAddress((void**)&wph, g_wph);

    cudaFuncSetAttribute(hgemm, cudaFuncAttributeMaxDynamicSharedMemorySize, SMEM_G);

    // 0) weight prep (fp32 -> fp16)
    prep_half_kernel<<<(C_ * C3 / 4 + 255) / 256, 256>>>(w_qkv, wqh, C_ * C3 / 4);
    prep_half_kernel<<<(C_ * C_ / 4 + 255) / 256, 256>>>(w_proj, wph, C_ * C_ / 4);

    // 1) QKV GEMM, 2-term fp16 split: (50176,384) @ (384,1152)
    {
        dim3 grid(C3 / 128, M_ROWS / 128);
        hgemm<<<grid, 512, SMEM_G>>>(x, wqh, qkv, M_ROWS, C3, C_, nullptr);
    }
    // 2) window attention -> y
    attn_kernel<<<B_ * NW * HEADS_, 64>>>(qkv, y);
    // 3) depthwise conv, += into y
    {
        long long total = (long long)B_ * Nn * (C_ / 4);
        conv_add_kernel<<<(unsigned)((total + 255) / 256), 256>>>(qkv, w_conv, b_conv, y);
    }
    // 4) proj GEMM, 2-term fp16 split (+bias) -> out
    {
        dim3 grid(C_ / 128, M_ROWS / 128);
        hgemm<<<grid, 512, SMEM_G>>>(y, wph, out, M_ROWS, C_, C_, b_proj);
    }
}